// round 6
// baseline (speedup 1.0000x reference)
#include <cuda_runtime.h>
#include <cfloat>

// Reverse cummax along axis 1 of [B=16, H=128, W=128, C=256] fp32.
// One thread per (b, w, c4) float4-column; walk h backward with running max.
// R5: identical to R3 (best: 128thr x 1024 CTAs, unroll-4) plus streaming
// cache hints isolated from prior confounds: __ldcs on loads, __stcs on
// stores (touch-once data; keep L2 occupancy for the read-ahead stream).

static constexpr int B = 16;
static constexpr int H = 128;
static constexpr int W = 128;
static constexpr int C = 256;
static constexpr int C4 = C / 4;            // 64 float4 per row
static constexpr int STRIDE_H = W * C4;     // 8192 float4 between h slices
static constexpr int COLS = B * W * C4;     // 131072 columns
static constexpr int PER_B = W * C4;        // 8192 columns per batch
static constexpr long PER_B_ELEMS = (long)H * W * C4;

__global__ void __launch_bounds__(128) rev_cummax_kernel(
    const float4* __restrict__ in, float4* __restrict__ out)
{
    int col = blockIdx.x * blockDim.x + threadIdx.x;

    int b   = col >> 13;            // col / 8192
    int rem = col & (PER_B - 1);
    long base = (long)b * PER_B_ELEMS + rem;

    float4 m = make_float4(-FLT_MAX, -FLT_MAX, -FLT_MAX, -FLT_MAX);

    #pragma unroll 4
    for (int h = H - 1; h >= 0; --h) {
        long idx = base + (long)h * STRIDE_H;
        float4 v = __ldcs(in + idx);
        m.x = fmaxf(m.x, v.x);
        m.y = fmaxf(m.y, v.y);
        m.z = fmaxf(m.z, v.z);
        m.w = fmaxf(m.w, v.w);
        __stcs(out + idx, m);
    }
}

extern "C" void kernel_launch(void* const* d_in, const int* in_sizes, int n_in,
                              void* d_out, int out_size)
{
    (void)in_sizes; (void)n_in; (void)out_size;
    const float4* in  = (const float4*)d_in[0];
    float4*       out = (float4*)d_out;

    const int threads = 128;
    const int blocks  = COLS / threads;  // 1024, exact
    rev_cummax_kernel<<<blocks, threads>>>(in, out);
}

// round 7
// speedup vs baseline: 1.1919x; 1.1919x over previous
#include <cuda_runtime.h>
#include <cfloat>

// Reverse cummax along axis 1 of [B=16, H=128, W=128, C=256] fp32.
// One thread per (b, w, c4) float4-column; walk h backward with running max.
// R6: exact R3 structure (best known: 128thr x 1024 CTAs, simple interleaved
// body, DEFAULT cache policy — .cs was a 30% regression) with unroll 4 -> 8,
// the last untested micro-axis in this configuration.

static constexpr int B = 16;
static constexpr int H = 128;
static constexpr int W = 128;
static constexpr int C = 256;
static constexpr int C4 = C / 4;            // 64 float4 per row
static constexpr int STRIDE_H = W * C4;     // 8192 float4 between h slices
static constexpr int COLS = B * W * C4;     // 131072 columns
static constexpr int PER_B = W * C4;        // 8192 columns per batch
static constexpr long PER_B_ELEMS = (long)H * W * C4;

__global__ void __launch_bounds__(128) rev_cummax_kernel(
    const float4* __restrict__ in, float4* __restrict__ out)
{
    int col = blockIdx.x * blockDim.x + threadIdx.x;

    int b   = col >> 13;            // col / 8192
    int rem = col & (PER_B - 1);
    long base = (long)b * PER_B_ELEMS + rem;

    float4 m = make_float4(-FLT_MAX, -FLT_MAX, -FLT_MAX, -FLT_MAX);

    #pragma unroll 8
    for (int h = H - 1; h >= 0; --h) {
        long idx = base + (long)h * STRIDE_H;
        float4 v = in[idx];
        m.x = fmaxf(m.x, v.x);
        m.y = fmaxf(m.y, v.y);
        m.z = fmaxf(m.z, v.z);
        m.w = fmaxf(m.w, v.w);
        out[idx] = m;
    }
}

extern "C" void kernel_launch(void* const* d_in, const int* in_sizes, int n_in,
                              void* d_out, int out_size)
{
    (void)in_sizes; (void)n_in; (void)out_size;
    const float4* in  = (const float4*)d_in[0];
    float4*       out = (float4*)d_out;

    const int threads = 128;
    const int blocks  = COLS / threads;  // 1024, exact
    rev_cummax_kernel<<<blocks, threads>>>(in, out);
}